// round 6
// baseline (speedup 1.0000x reference)
#include <cuda_runtime.h>

#define NB 64
#define CHN 3
#define HH 256
#define WW 256
#define TAP 43
#define PADT 21                 // TAP/2
#define PW (WW + 2*PADT)        // 298
#define ROWP 304                // padded row capacity (floats) for swizzle headroom
#define ROWS1 8
#define R2 64
#define LR2 (R2 + 2*PADT)       // 106

typedef unsigned long long u64;

// ---------------- per-image parameters + scratch ----------------
__device__ float d_M[NB][12];       // rows 0..2 of 4x4 color matrix
__device__ float d_k2[NB][88];      // taps: [0..43]=ke (k0..k42,0), [44..87]=ko (0,k0..k42)
__device__ float d_misc[NB][4];     // sigma, cx, cy, half
__device__ float d_tmp[(size_t)NB * CHN * HH * WW];  // intermediate after h-conv

// ---------------- packed f32x2 helpers ----------------
__device__ __forceinline__ u64 ffma2(u64 a, u64 b, u64 c) {
    u64 d;
    asm("fma.rn.f32x2 %0, %1, %2, %3;" : "=l"(d) : "l"(a), "l"(b), "l"(c));
    return d;
}
__device__ __forceinline__ void split2(u64 v, float& lo, float& hi) {
    asm("mov.b64 {%0, %1}, %2;" : "=f"(lo), "=f"(hi) : "l"(v));
}

// ---------------- core: 8 consecutive outputs of 43-tap conv ----------------
// Window pairs: b2[swz(u0+i)] = (v[2i], v[2i+1]).
// out[2q]   = sum_m ke[m] . V[u0+q+m]   (ke[m] = (k[2m], k[2m+1]), k43=0)
// out[2q+1] = sum_m ko[m] . V[u0+q+m]   (ko[m] = (k[2m-1], k[2m]), k-1=0)
template<bool SWZ>
__device__ __forceinline__ void conv8(const u64* __restrict__ b2, int u0,
                                      const u64* __restrict__ ke,
                                      const u64* __restrict__ ko,
                                      float out8[8]) {
    u64 W[5], accE[4], accO[4];
#pragma unroll
    for (int j = 0; j < 5; j++) {
        int u = u0 + j;
        int su = SWZ ? (u ^ ((u >> 4) & 3)) : u;
        W[j] = b2[su];
    }
#pragma unroll
    for (int q = 0; q < 4; q++) { accE[q] = 0ull; accO[q] = 0ull; }

#pragma unroll
    for (int m = 0; m < 22; m++) {
        u64 te = ke[m];            // broadcast LDS.64, conflict-free
        u64 to = ko[m];
        accE[0] = ffma2(te, W[0], accE[0]);
        accO[0] = ffma2(to, W[0], accO[0]);
        accE[1] = ffma2(te, W[1], accE[1]);
        accO[1] = ffma2(to, W[1], accO[1]);
        accE[2] = ffma2(te, W[2], accE[2]);
        accO[2] = ffma2(to, W[2], accO[2]);
        accE[3] = ffma2(te, W[3], accE[3]);
        accO[3] = ffma2(to, W[3], accO[3]);
        W[0] = W[1]; W[1] = W[2]; W[2] = W[3]; W[3] = W[4];
        if (m < 20) {
            int u = u0 + m + 5;
            int su = SWZ ? (u ^ ((u >> 4) & 3)) : u;
            W[4] = b2[su];
        }
    }
#pragma unroll
    for (int q = 0; q < 4; q++) {
        float l, h;
        split2(accE[q], l, h); out8[2 * q]     = l + h;
        split2(accO[q], l, h); out8[2 * q + 1] = l + h;
    }
}

// ---------------- setup ----------------
__device__ __forceinline__ void mm4(const float* A, const float* B, float* Co) {
#pragma unroll
    for (int i = 0; i < 4; i++)
#pragma unroll
        for (int j = 0; j < 4; j++) {
            float s = 0.f;
#pragma unroll
            for (int q = 0; q < 4; q++) s += A[i*4+q] * B[q*4+j];
            Co[i*4+j] = s;
        }
}

__global__ void setup_kernel(const float* __restrict__ gates,
                             const float* __restrict__ gauss,
                             const float* __restrict__ unif,
                             const float* __restrict__ fbank) {
    int i = threadIdx.x;
    if (i >= NB) return;
    const float P = 1.0f;
    const float s3 = 0.57735026918962576f;
    const float third = 1.0f / 3.0f;
    const float* gt = gates + i * 11;
    const float* gs = gauss + i * 8;
    const float* un = unif + i * 4;

    float b = (gt[0] < P) ? gs[0] * 0.2f : 0.0f;
    float c = (gt[1] < P) ? exp2f(gs[1] * 0.5f) : 1.0f;
    float Cm[16];
#pragma unroll
    for (int q = 0; q < 16; q++) Cm[q] = 0.f;
    Cm[0] = c; Cm[5] = c; Cm[10] = c; Cm[15] = 1.0f;
    Cm[3] = c * b; Cm[7] = c * b; Cm[11] = c * b;

    float A[16], T2[16];
    float ilf = (gt[2] < P) ? floorf(un[0] * 2.0f) : 0.0f;
#pragma unroll
    for (int r = 0; r < 4; r++)
#pragma unroll
        for (int cc = 0; cc < 4; cc++) {
            float vv = (r < 3 && cc < 3) ? third : 0.f;
            A[r*4+cc] = ((r == cc) ? 1.f : 0.f) - 2.f * vv * ilf;
        }
    mm4(A, Cm, T2);
#pragma unroll
    for (int q = 0; q < 16; q++) Cm[q] = T2[q];

    float th = (gt[3] < P) ? (un[1] * 2.0f - 1.0f) * 3.14159265358979323846f : 0.0f;
    float co = cosf(th), si = sinf(th);
    float K[9] = {0.f, -s3, s3, s3, 0.f, -s3, -s3, s3, 0.f};
#pragma unroll
    for (int r = 0; r < 4; r++)
#pragma unroll
        for (int cc = 0; cc < 4; cc++) {
            float v;
            if (r < 3 && cc < 3)
                v = (1.f - co) * third + co * ((r == cc) ? 1.f : 0.f) + si * K[r*3+cc];
            else
                v = (r == cc) ? 1.f : 0.f;
            A[r*4+cc] = v;
        }
    mm4(A, Cm, T2);
#pragma unroll
    for (int q = 0; q < 16; q++) Cm[q] = T2[q];

    float ss = (gt[4] < P) ? exp2f(gs[2] * 1.0f) : 1.0f;
#pragma unroll
    for (int r = 0; r < 4; r++)
#pragma unroll
        for (int cc = 0; cc < 4; cc++) {
            float vv = (r < 3 && cc < 3) ? third : 0.f;
            float id = (r == cc) ? 1.f : 0.f;
            A[r*4+cc] = vv + (id - vv) * ss;
        }
    mm4(A, Cm, T2);
#pragma unroll
    for (int q = 0; q < 12; q++) d_M[i][q] = T2[q];

    const float ep0 = 10.0f / 13.0f, epo = 1.0f / 13.0f;
    float g0 = 1.f, g1 = 1.f, g2 = 1.f, g3 = 1.f;
#pragma unroll
    for (int bnd = 0; bnd < 4; bnd++) {
        float ti = (gt[5 + bnd] < P) ? exp2f(gs[3 + bnd] * 1.0f) : 1.0f;
        float t0 = 1.f, t1 = 1.f, t2 = 1.f, t3 = 1.f;
        if (bnd == 0) t0 = ti; else if (bnd == 1) t1 = ti;
        else if (bnd == 2) t2 = ti; else t3 = ti;
        float sum = ep0 * t0 * t0 + epo * (t1 * t1 + t2 * t2 + t3 * t3);
        float inv = rsqrtf(sum);
        g0 *= t0 * inv; g1 *= t1 * inv; g2 *= t2 * inv; g3 *= t3 * inv;
    }
    float kk[44];
    for (int j = 0; j < TAP; j++)
        kk[j] = g0 * fbank[j] + g1 * fbank[TAP + j]
              + g2 * fbank[2 * TAP + j] + g3 * fbank[3 * TAP + j];
    kk[43] = 0.f;
    // ke: k0..k42, 0   |   ko: 0, k0..k42
    for (int j = 0; j < 44; j++) d_k2[i][j] = kk[j];
    d_k2[i][44] = 0.f;
    for (int j = 0; j < 43; j++) d_k2[i][45 + j] = kk[j];

    d_misc[i][0] = (gt[9] < P) ? fabsf(gs[7]) * 0.1f : 0.0f;
    d_misc[i][1] = un[2];
    d_misc[i][2] = un[3];
    d_misc[i][3] = (gt[10] < P) ? 0.25f : 0.0f;
}

// ---------------- pass1: color transform + horizontal conv ----------------
__global__ void __launch_bounds__(256) pass1_kernel(const float* __restrict__ img) {
    __shared__ __align__(16) float sp[CHN][ROWS1][ROWP];   // swizzled rows
    __shared__ __align__(16) float Ms[12];
    __shared__ __align__(16) float ksm[88];
    const int n = blockIdx.y;
    const int y0 = blockIdx.x * ROWS1;
    const int tid = threadIdx.x;

    if (tid < 12) Ms[tid] = d_M[n][tid];
    if (tid < 88) ksm[tid] = d_k2[n][tid];
    __syncthreads();

    float M00 = Ms[0], M01 = Ms[1], M02 = Ms[2], M03 = Ms[3];
    float M10 = Ms[4], M11 = Ms[5], M12 = Ms[6], M13 = Ms[7];
    float M20 = Ms[8], M21 = Ms[9], M22 = Ms[10], M23 = Ms[11];

    const size_t baseN = (size_t)n * CHN * HH * WW;

    // load reflect-padded rows + color transform into swizzled smem
    for (int p = tid; p < ROWS1 * PW; p += 256) {
        int r = p / PW;
        int j = p - r * PW;
        int xs = j - PADT;
        xs = (xs < 0) ? -xs : ((xs >= WW) ? (2 * WW - 2 - xs) : xs);
        int y = y0 + r;
        const float* pix = img + baseN + (size_t)y * WW + xs;
        float r0 = pix[0];
        float r1 = pix[HH * WW];
        float r2 = pix[2 * HH * WW];
        int u = j >> 1;
        int slot = 2 * (u ^ ((u >> 4) & 3)) + (j & 1);
        sp[0][r][slot] = M00 * r0 + M01 * r1 + M02 * r2 + M03;
        sp[1][r][slot] = M10 * r0 + M11 * r1 + M12 * r2 + M13;
        sp[2][r][slot] = M20 * r0 + M21 * r1 + M22 * r2 + M23;
    }
    __syncthreads();

    const u64* ke = reinterpret_cast<const u64*>(ksm);        // 22 pairs
    const u64* ko = reinterpret_cast<const u64*>(ksm + 44);   // 22 pairs
    const int lane = tid & 31;
    const int r = tid >> 5;
    const int x0 = lane * 8;
    const int y = y0 + r;

#pragma unroll
    for (int c = 0; c < CHN; c++) {
        const u64* b2 = reinterpret_cast<const u64*>(&sp[c][r][0]);
        float o8[8];
        conv8<true>(b2, lane * 4, ke, ko, o8);
        float* o = d_tmp + baseN + (size_t)c * HH * WW + (size_t)y * WW + x0;
        *reinterpret_cast<float4*>(o)     = make_float4(o8[0], o8[1], o8[2], o8[3]);
        *reinterpret_cast<float4*>(o + 4) = make_float4(o8[4], o8[5], o8[6], o8[7]);
    }
}

// ---------------- pass2: vertical conv + noise + cutout ----------------
__global__ void __launch_bounds__(256) pass2_kernel(const float* __restrict__ noise,
                                                    float* __restrict__ out) {
    extern __shared__ __align__(16) float s2[];   // transposed tile: s2[x*106 + yrow]
    __shared__ __align__(16) float ksm[88];
    __shared__ float ms[4];
    const int nc = blockIdx.y;        // n*3 + c
    const int n = nc / 3;
    const int y0 = blockIdx.x * R2;
    const int tid = threadIdx.x;

    if (tid < 88) ksm[tid] = d_k2[n][tid];
    if (tid < 4) ms[tid] = d_misc[n][tid];

    const size_t base = (size_t)nc * HH * WW;
    for (int p = tid; p < LR2 * WW; p += 256) {
        int row = p >> 8;
        int x = p & 255;
        int ys = y0 + row - PADT;
        ys = (ys < 0) ? -ys : ((ys >= HH) ? (2 * HH - 2 - ys) : ys);
        s2[x * LR2 + row] = d_tmp[base + (size_t)ys * WW + x];
    }
    __syncthreads();

    const u64* ke = reinterpret_cast<const u64*>(ksm);
    const u64* ko = reinterpret_cast<const u64*>(ksm + 44);
    const float sigma = ms[0], cx = ms[1], cy = ms[2], half = ms[3];
    const float coordx = ((float)tid + 0.5f) * (1.0f / WW);
    const bool keepx = fabsf(coordx - cx) >= half;

    const u64* b2 = reinterpret_cast<const u64*>(s2);
    const int ubase = tid * (LR2 / 2);   // 53 ulls per column

#pragma unroll
    for (int g = 0; g < R2 / 8; g++) {
        float o8[8];
        conv8<false>(b2, ubase + g * 4, ke, ko, o8);
#pragma unroll
        for (int rr = 0; rr < 8; rr++) {
            int yy = y0 + g * 8 + rr;
            size_t idx = base + (size_t)yy * WW + tid;
            float val = o8[rr] + noise[idx] * sigma;
            float coordy = ((float)yy + 0.5f) * (1.0f / HH);
            bool keep = keepx || (fabsf(coordy - cy) >= half);
            out[idx] = keep ? val : 0.0f;
        }
    }
}

// ---------------- launch ----------------
extern "C" void kernel_launch(void* const* d_in, const int* in_sizes, int n_in,
                              void* d_out, int out_size) {
    const float* images = (const float*)d_in[0];
    const float* gates  = (const float*)d_in[1];
    const float* gauss  = (const float*)d_in[2];
    const float* unif   = (const float*)d_in[3];
    const float* noise  = (const float*)d_in[4];
    const float* fbank  = (const float*)d_in[5];
    float* out = (float*)d_out;

    setup_kernel<<<1, 64>>>(gates, gauss, unif, fbank);
    pass1_kernel<<<dim3(HH / ROWS1, NB), 256>>>(images);

    cudaFuncSetAttribute(pass2_kernel, cudaFuncAttributeMaxDynamicSharedMemorySize,
                         LR2 * WW * (int)sizeof(float));
    pass2_kernel<<<dim3(HH / R2, NB * CHN), 256, LR2 * WW * sizeof(float)>>>(noise, out);
}

// round 7
// speedup vs baseline: 1.0296x; 1.0296x over previous
#include <cuda_runtime.h>

#define NB 64
#define CHN 3
#define HH 256
#define WW 256
#define TAP 43
#define PADT 21                 // TAP/2
#define PW (WW + 2*PADT)        // 298
#define ROWP 304                // swizzle headroom (max slot 303)
#define ROWS1 8
#define R2 64
#define LR2 (R2 + 2*PADT)       // 106

__device__ float d_tmp[(size_t)NB * CHN * HH * WW];  // intermediate after h-conv

// ---------------- folded symmetric 43-tap conv: 8 consecutive outputs ----------
// V(j) = SWZ ? b[(o0+j) ^ (((o0+j)>>5)&7)] : b[(o0+j)*STRIDE]
// out[q] = sum_{j=0}^{20} kt[j]*(v[o0+q+j] + v[o0+q+42-j]) + kt[21]*v[o0+q+21]
template<bool SWZ, int STRIDE>
__device__ __forceinline__ void conv8f(const float* __restrict__ b, int o0,
                                       const float kt[22], float out8[8]) {
    float L[8], R[8], acc[8];
#pragma unroll
    for (int q = 0; q < 8; q++) {
        int u = o0 + q;
        L[q] = SWZ ? b[u ^ ((u >> 5) & 7)] : b[u * STRIDE];
    }
#pragma unroll
    for (int q = 0; q < 8; q++) {
        int u = o0 + 42 + q;
        R[q] = SWZ ? b[u ^ ((u >> 5) & 7)] : b[u * STRIDE];
    }
#pragma unroll
    for (int q = 0; q < 8; q++) acc[q] = 0.f;

#pragma unroll
    for (int j = 0; j < 21; j++) {
        float kj = kt[j];
#pragma unroll
        for (int q = 0; q < 8; q++) acc[q] = fmaf(kj, L[q] + R[q], acc[q]);
        // slide L right: L[q] <- v[o0+q+j+1]  (needed through j=20 to leave L = v[o0+q+21])
#pragma unroll
        for (int q = 0; q < 7; q++) L[q] = L[q + 1];
        {
            int u = o0 + j + 8;
            L[7] = SWZ ? b[u ^ ((u >> 5) & 7)] : b[u * STRIDE];
        }
        if (j < 20) {
            // slide R left: R[q] <- v[o0+q+41-j]
#pragma unroll
            for (int q = 7; q > 0; q--) R[q] = R[q - 1];
            int u = o0 + 41 - j;
            R[0] = SWZ ? b[u ^ ((u >> 5) & 7)] : b[u * STRIDE];
        }
    }
#pragma unroll
    for (int q = 0; q < 8; q++) out8[q] = fmaf(kt[21], L[q], acc[q]);
}

// ---------------- per-block parameter computation ----------------
__device__ __forceinline__ float tap_value(int j, int n,
                                           const float* __restrict__ gates,
                                           const float* __restrict__ gauss,
                                           const float* __restrict__ fbank) {
    const float P = 1.0f;
    const float* gt = gates + n * 11;
    const float* gs = gauss + n * 8;
    const float ep0 = 10.0f / 13.0f, epo = 1.0f / 13.0f;
    float g0 = 1.f, g1 = 1.f, g2 = 1.f, g3 = 1.f;
#pragma unroll
    for (int bnd = 0; bnd < 4; bnd++) {
        float ti = (gt[5 + bnd] < P) ? exp2f(gs[3 + bnd] * 1.0f) : 1.0f;
        float t0 = 1.f, t1 = 1.f, t2 = 1.f, t3 = 1.f;
        if (bnd == 0) t0 = ti; else if (bnd == 1) t1 = ti;
        else if (bnd == 2) t2 = ti; else t3 = ti;
        float sum = ep0 * t0 * t0 + epo * (t1 * t1 + t2 * t2 + t3 * t3);
        float inv = rsqrtf(sum);
        g0 *= t0 * inv; g1 *= t1 * inv; g2 *= t2 * inv; g3 *= t3 * inv;
    }
    return g0 * fbank[j] + g1 * fbank[TAP + j]
         + g2 * fbank[2 * TAP + j] + g3 * fbank[3 * TAP + j];
}

__device__ __forceinline__ void mm4(const float* A, const float* B, float* Co) {
#pragma unroll
    for (int i = 0; i < 4; i++)
#pragma unroll
        for (int j = 0; j < 4; j++) {
            float s = 0.f;
#pragma unroll
            for (int q = 0; q < 4; q++) s += A[i*4+q] * B[q*4+j];
            Co[i*4+j] = s;
        }
}

__device__ void compute_color_matrix(int n, const float* __restrict__ gates,
                                     const float* __restrict__ gauss,
                                     const float* __restrict__ unif,
                                     float* __restrict__ Mout /*12 floats*/) {
    const float P = 1.0f;
    const float s3 = 0.57735026918962576f;
    const float third = 1.0f / 3.0f;
    const float* gt = gates + n * 11;
    const float* gs = gauss + n * 8;
    const float* un = unif + n * 4;

    float b = (gt[0] < P) ? gs[0] * 0.2f : 0.0f;
    float c = (gt[1] < P) ? exp2f(gs[1] * 0.5f) : 1.0f;
    float Cm[16];
#pragma unroll
    for (int q = 0; q < 16; q++) Cm[q] = 0.f;
    Cm[0] = c; Cm[5] = c; Cm[10] = c; Cm[15] = 1.0f;
    Cm[3] = c * b; Cm[7] = c * b; Cm[11] = c * b;

    float A[16], T2[16];
    float ilf = (gt[2] < P) ? floorf(un[0] * 2.0f) : 0.0f;
#pragma unroll
    for (int r = 0; r < 4; r++)
#pragma unroll
        for (int cc = 0; cc < 4; cc++) {
            float vv = (r < 3 && cc < 3) ? third : 0.f;
            A[r*4+cc] = ((r == cc) ? 1.f : 0.f) - 2.f * vv * ilf;
        }
    mm4(A, Cm, T2);
#pragma unroll
    for (int q = 0; q < 16; q++) Cm[q] = T2[q];

    float th = (gt[3] < P) ? (un[1] * 2.0f - 1.0f) * 3.14159265358979323846f : 0.0f;
    float co = cosf(th), si = sinf(th);
    float K[9] = {0.f, -s3, s3, s3, 0.f, -s3, -s3, s3, 0.f};
#pragma unroll
    for (int r = 0; r < 4; r++)
#pragma unroll
        for (int cc = 0; cc < 4; cc++) {
            float v;
            if (r < 3 && cc < 3)
                v = (1.f - co) * third + co * ((r == cc) ? 1.f : 0.f) + si * K[r*3+cc];
            else
                v = (r == cc) ? 1.f : 0.f;
            A[r*4+cc] = v;
        }
    mm4(A, Cm, T2);
#pragma unroll
    for (int q = 0; q < 16; q++) Cm[q] = T2[q];

    float ss = (gt[4] < P) ? exp2f(gs[2] * 1.0f) : 1.0f;
#pragma unroll
    for (int r = 0; r < 4; r++)
#pragma unroll
        for (int cc = 0; cc < 4; cc++) {
            float vv = (r < 3 && cc < 3) ? third : 0.f;
            float id = (r == cc) ? 1.f : 0.f;
            A[r*4+cc] = vv + (id - vv) * ss;
        }
    mm4(A, Cm, T2);
#pragma unroll
    for (int q = 0; q < 12; q++) Mout[q] = T2[q];
}

// ---------------- pass1: color transform + horizontal conv ----------------
__global__ void __launch_bounds__(256) pass1_kernel(const float* __restrict__ img,
                                                    const float* __restrict__ gates,
                                                    const float* __restrict__ gauss,
                                                    const float* __restrict__ unif,
                                                    const float* __restrict__ fbank) {
    __shared__ __align__(16) float sp[CHN][ROWS1][ROWP];   // swizzled rows
    __shared__ __align__(16) float prm[34];                // [0..11]=M, [12..33]=taps
    const int n = blockIdx.y;
    const int y0 = blockIdx.x * ROWS1;
    const int tid = threadIdx.x;

    if (tid < 22) prm[12 + tid] = tap_value(tid, n, gates, gauss, fbank);
    if (tid == 224) compute_color_matrix(n, gates, gauss, unif, &prm[0]);
    __syncthreads();

    const float M00 = prm[0], M01 = prm[1], M02 = prm[2],  M03 = prm[3];
    const float M10 = prm[4], M11 = prm[5], M12 = prm[6],  M13 = prm[7];
    const float M20 = prm[8], M21 = prm[9], M22 = prm[10], M23 = prm[11];

    const size_t baseN = (size_t)n * CHN * HH * WW;

    // reflect-padded rows + color transform into swizzled smem
    for (int p = tid; p < ROWS1 * PW; p += 256) {
        int r = p / PW;
        int j = p - r * PW;
        int xs = j - PADT;
        xs = (xs < 0) ? -xs : ((xs >= WW) ? (2 * WW - 2 - xs) : xs);
        int y = y0 + r;
        const float* pix = img + baseN + (size_t)y * WW + xs;
        float r0 = pix[0];
        float r1 = pix[HH * WW];
        float r2 = pix[2 * HH * WW];
        int slot = j ^ ((j >> 5) & 7);
        sp[0][r][slot] = M00 * r0 + M01 * r1 + M02 * r2 + M03;
        sp[1][r][slot] = M10 * r0 + M11 * r1 + M12 * r2 + M13;
        sp[2][r][slot] = M20 * r0 + M21 * r1 + M22 * r2 + M23;
    }

    float ktr[22];
#pragma unroll
    for (int q = 0; q < 22; q++) ktr[q] = prm[12 + q];
    __syncthreads();

    const int lane = tid & 31;
    const int r = tid >> 5;
    const int x0 = lane * 8;
    const int y = y0 + r;

#pragma unroll
    for (int c = 0; c < CHN; c++) {
        float o8[8];
        conv8f<true, 1>(&sp[c][r][0], x0, ktr, o8);
        float* o = d_tmp + baseN + (size_t)c * HH * WW + (size_t)y * WW + x0;
        *reinterpret_cast<float4*>(o)     = make_float4(o8[0], o8[1], o8[2], o8[3]);
        *reinterpret_cast<float4*>(o + 4) = make_float4(o8[4], o8[5], o8[6], o8[7]);
    }
}

// ---------------- pass2: vertical conv + noise + cutout ----------------
__global__ void __launch_bounds__(256) pass2_kernel(const float* __restrict__ noise,
                                                    float* __restrict__ out,
                                                    const float* __restrict__ gates,
                                                    const float* __restrict__ gauss,
                                                    const float* __restrict__ unif,
                                                    const float* __restrict__ fbank) {
    extern __shared__ __align__(16) float s2[];   // row-major tile [LR2][256]
    __shared__ __align__(16) float prm[26];       // [0..21]=taps, [22..25]=sigma,cx,cy,half
    const int nc = blockIdx.y;        // n*3 + c
    const int n = nc / 3;
    const int y0 = blockIdx.x * R2;
    const int tid = threadIdx.x;

    if (tid < 22) prm[tid] = tap_value(tid, n, gates, gauss, fbank);
    if (tid == 32) {
        const float P = 1.0f;
        const float* gt = gates + n * 11;
        prm[22] = (gt[9] < P) ? fabsf(gauss[n * 8 + 7]) * 0.1f : 0.0f;  // sigma
        prm[23] = unif[n * 4 + 2];                                       // cx
        prm[24] = unif[n * 4 + 3];                                       // cy
        prm[25] = (gt[10] < P) ? 0.25f : 0.0f;                           // size*0.5
    }

    const size_t base = (size_t)nc * HH * WW;
    for (int p = tid; p < LR2 * WW; p += 256) {
        int row = p >> 8;
        int x = p & 255;
        int ys = y0 + row - PADT;
        ys = (ys < 0) ? -ys : ((ys >= HH) ? (2 * HH - 2 - ys) : ys);
        s2[p] = d_tmp[base + (size_t)ys * WW + x];
    }
    __syncthreads();

    float ktr[22];
#pragma unroll
    for (int q = 0; q < 22; q++) ktr[q] = prm[q];
    const float sigma = prm[22], cx = prm[23], cy = prm[24], half = prm[25];
    const float coordx = ((float)tid + 0.5f) * (1.0f / WW);
    const bool keepx = fabsf(coordx - cx) >= half;

#pragma unroll
    for (int g = 0; g < R2 / 8; g++) {
        float o8[8];
        conv8f<false, WW>(s2 + tid, g * 8, ktr, o8);
#pragma unroll
        for (int rr = 0; rr < 8; rr++) {
            int yy = y0 + g * 8 + rr;
            size_t idx = base + (size_t)yy * WW + tid;
            float val = o8[rr] + noise[idx] * sigma;
            float coordy = ((float)yy + 0.5f) * (1.0f / HH);
            bool keep = keepx || (fabsf(coordy - cy) >= half);
            out[idx] = keep ? val : 0.0f;
        }
    }
}

// ---------------- launch ----------------
extern "C" void kernel_launch(void* const* d_in, const int* in_sizes, int n_in,
                              void* d_out, int out_size) {
    const float* images = (const float*)d_in[0];
    const float* gates  = (const float*)d_in[1];
    const float* gauss  = (const float*)d_in[2];
    const float* unif   = (const float*)d_in[3];
    const float* noise  = (const float*)d_in[4];
    const float* fbank  = (const float*)d_in[5];
    float* out = (float*)d_out;

    pass1_kernel<<<dim3(HH / ROWS1, NB), 256>>>(images, gates, gauss, unif, fbank);

    cudaFuncSetAttribute(pass2_kernel, cudaFuncAttributeMaxDynamicSharedMemorySize,
                         LR2 * WW * (int)sizeof(float));
    pass2_kernel<<<dim3(HH / R2, NB * CHN), 256, LR2 * WW * sizeof(float)>>>(
        noise, out, gates, gauss, unif, fbank);
}